// round 4
// baseline (speedup 1.0000x reference)
#include <cuda_runtime.h>
#include <math.h>

#define NUM_CITIES 88
#define NC4        22          // 88 / 4 float4 groups per row
#define NUM_YEARS  6
#define N_ROWS     200000

#define MAIN_BLOCK 352         // 22 * 16 -> every block is column-group aligned
#define MAIN_GRID  592         // 148 SMs * 4 resident blocks, one wave

// Scratch accumulators (no cudaMalloc allowed)
__device__ float g_colsum[NUM_CITIES];
__device__ float g_scalar;

__global__ void zero_kernel() {
    int t = threadIdx.x;
    if (t < NUM_CITIES) g_colsum[t] = 0.0f;
    if (t == 0) g_scalar = 0.0f;
}

__global__ __launch_bounds__(MAIN_BLOCK)
void main_kernel(const float4* __restrict__ G4,
                 const float4* __restrict__ D4,
                 const float4* __restrict__ W4,
                 const float*  __restrict__ U,
                 const float*  __restrict__ OUT)
{
    const int tid    = blockIdx.x * MAIN_BLOCK + threadIdx.x;
    const int total  = gridDim.x * MAIN_BLOCK;          // multiple of 22
    const int lanes  = total / NC4;                     // row-stride lanes
    const int cg     = tid % NC4;                       // fixed column group
    const int lane   = tid / NC4;

    // --- per-thread accumulators ---
    float c0 = 0.f, c1 = 0.f, c2 = 0.f, c3 = 0.f;       // |G| column partials
    float s  = 0.f;                                     // scalar loss partial

    // Term 1: ||U[:, :5] - out[:, :5]||_F^2  (small: 9.6 MB)
    for (int r = tid; r < N_ROWS; r += total) {
        const float* u = U   + r * NUM_YEARS;
        const float* o = OUT + r * NUM_YEARS;
        #pragma unroll
        for (int j = 0; j < NUM_YEARS - 1; j++) {
            float d = u[j] - o[j];
            s += d * d;
        }
    }

    // Main stream: G, D, w  (211 MB) — each thread stays in one 4-col group
    for (int r = lane; r < N_ROWS; r += lanes) {
        int i = r * NC4 + cg;
        float4 g = G4[i];
        float4 d = D4[i];
        float4 w = W4[i];

        // column L1 of |G|
        c0 += fabsf(g.x); c1 += fabsf(g.y);
        c2 += fabsf(g.z); c3 += fabsf(g.w);

        // 100 * ||G - w*D||^2
        float r0 = fmaf(-w.x, d.x, g.x);
        float r1 = fmaf(-w.y, d.y, g.y);
        float r2 = fmaf(-w.z, d.z, g.z);
        float r3 = fmaf(-w.w, d.w, g.w);
        s += 100.0f * (r0*r0 + r1*r1 + r2*r2 + r3*r3);

        // 0.01 * ||w||^2
        s += 0.01f * (w.x*w.x + w.y*w.y + w.z*w.z + w.w*w.w);

        // 100 * sum(min(G, 0))
        s += 100.0f * (fminf(g.x, 0.f) + fminf(g.y, 0.f)
                     + fminf(g.z, 0.f) + fminf(g.w, 0.f));
    }

    // --- block-level reduction ---
    __shared__ float scol[NUM_CITIES];
    __shared__ float swarp[MAIN_BLOCK / 32];

    if (threadIdx.x < NUM_CITIES) scol[threadIdx.x] = 0.0f;
    __syncthreads();

    // column partials: 16 threads per shared slot, once per block
    atomicAdd(&scol[cg * 4 + 0], c0);
    atomicAdd(&scol[cg * 4 + 1], c1);
    atomicAdd(&scol[cg * 4 + 2], c2);
    atomicAdd(&scol[cg * 4 + 3], c3);

    // scalar: warp shuffle reduce
    #pragma unroll
    for (int off = 16; off > 0; off >>= 1)
        s += __shfl_xor_sync(0xFFFFFFFF, s, off);
    if ((threadIdx.x & 31) == 0) swarp[threadIdx.x >> 5] = s;
    __syncthreads();

    if (threadIdx.x < NUM_CITIES)
        atomicAdd(&g_colsum[threadIdx.x], scol[threadIdx.x]);

    if (threadIdx.x == 0) {
        float bs = 0.f;
        #pragma unroll
        for (int wv = 0; wv < MAIN_BLOCK / 32; wv++) bs += swarp[wv];
        atomicAdd(&g_scalar, bs);
    }
}

__global__ void finalize_kernel(float* __restrict__ out)
{
    __shared__ float sh[128];
    int t = threadIdx.x;
    float v = (t < NUM_CITIES) ? logf(g_colsum[t]) : 0.0f;
    sh[t] = v;
    __syncthreads();
    for (int off = 64; off > 0; off >>= 1) {
        if (t < off) sh[t] += sh[t + off];
        __syncthreads();
    }
    if (t == 0) {
        // loss = scalar_terms + stddeve^2 * lgg   (stddeve^2 = 1e-4)
        out[0] = g_scalar + 1.0e-4f * sh[0];
    }
}

extern "C" void kernel_launch(void* const* d_in, const int* in_sizes, int n_in,
                              void* d_out, int out_size)
{
    // metadata order: G, out, U, V, D, w   (V unused)
    const float4* G4  = (const float4*)d_in[0];
    const float*  OUT = (const float*) d_in[1];
    const float*  U   = (const float*) d_in[2];
    const float4* D4  = (const float4*)d_in[4];
    const float4* W4  = (const float4*)d_in[5];
    float* out = (float*)d_out;

    zero_kernel<<<1, 96>>>();
    main_kernel<<<MAIN_GRID, MAIN_BLOCK>>>(G4, D4, W4, U, OUT);
    finalize_kernel<<<1, 128>>>(out);
}

// round 5
// speedup vs baseline: 1.0015x; 1.0015x over previous
#include <cuda_runtime.h>
#include <math.h>

#define NUM_CITIES 88
#define NC4        22          // 88 / 4 float4 groups per row
#define NUM_YEARS  6
#define N_ROWS     200000

#define MAIN_BLOCK 352         // 22 * 16 -> every block is column-group aligned
#define MAIN_GRID  592         // 148 SMs * 4 resident blocks, one wave

// Scratch accumulators (no cudaMalloc allowed)
__device__ float g_colsum[NUM_CITIES];
__device__ float g_scalar;

__global__ void zero_kernel() {
    int t = threadIdx.x;
    if (t < NUM_CITIES) g_colsum[t] = 0.0f;
    if (t == 0) g_scalar = 0.0f;
}

__global__ __launch_bounds__(MAIN_BLOCK)
void main_kernel(const float4* __restrict__ G4,
                 const float4* __restrict__ D4,
                 const float4* __restrict__ W4,
                 const float*  __restrict__ U,
                 const float*  __restrict__ OUT)
{
    const int tid    = blockIdx.x * MAIN_BLOCK + threadIdx.x;
    const int total  = gridDim.x * MAIN_BLOCK;          // multiple of 22
    const int lanes  = total / NC4;                     // row-stride lanes
    const int cg     = tid % NC4;                       // fixed column group
    const int lane   = tid / NC4;

    // --- per-thread accumulators ---
    float c0 = 0.f, c1 = 0.f, c2 = 0.f, c3 = 0.f;       // |G| column partials
    float s  = 0.f;                                     // scalar loss partial

    // Term 1: ||U[:, :5] - out[:, :5]||_F^2  (small: 9.6 MB)
    for (int r = tid; r < N_ROWS; r += total) {
        const float* u = U   + r * NUM_YEARS;
        const float* o = OUT + r * NUM_YEARS;
        #pragma unroll
        for (int j = 0; j < NUM_YEARS - 1; j++) {
            float d = u[j] - o[j];
            s += d * d;
        }
    }

    // Main stream: G, D, w  (211 MB) — each thread stays in one 4-col group
    for (int r = lane; r < N_ROWS; r += lanes) {
        int i = r * NC4 + cg;
        float4 g = G4[i];
        float4 d = D4[i];
        float4 w = W4[i];

        // column L1 of |G|
        c0 += fabsf(g.x); c1 += fabsf(g.y);
        c2 += fabsf(g.z); c3 += fabsf(g.w);

        // 100 * ||G - w*D||^2
        float r0 = fmaf(-w.x, d.x, g.x);
        float r1 = fmaf(-w.y, d.y, g.y);
        float r2 = fmaf(-w.z, d.z, g.z);
        float r3 = fmaf(-w.w, d.w, g.w);
        s += 100.0f * (r0*r0 + r1*r1 + r2*r2 + r3*r3);

        // 0.01 * ||w||^2
        s += 0.01f * (w.x*w.x + w.y*w.y + w.z*w.z + w.w*w.w);

        // 100 * sum(min(G, 0))
        s += 100.0f * (fminf(g.x, 0.f) + fminf(g.y, 0.f)
                     + fminf(g.z, 0.f) + fminf(g.w, 0.f));
    }

    // --- block-level reduction ---
    __shared__ float scol[NUM_CITIES];
    __shared__ float swarp[MAIN_BLOCK / 32];

    if (threadIdx.x < NUM_CITIES) scol[threadIdx.x] = 0.0f;
    __syncthreads();

    // column partials: 16 threads per shared slot, once per block
    atomicAdd(&scol[cg * 4 + 0], c0);
    atomicAdd(&scol[cg * 4 + 1], c1);
    atomicAdd(&scol[cg * 4 + 2], c2);
    atomicAdd(&scol[cg * 4 + 3], c3);

    // scalar: warp shuffle reduce
    #pragma unroll
    for (int off = 16; off > 0; off >>= 1)
        s += __shfl_xor_sync(0xFFFFFFFF, s, off);
    if ((threadIdx.x & 31) == 0) swarp[threadIdx.x >> 5] = s;
    __syncthreads();

    if (threadIdx.x < NUM_CITIES)
        atomicAdd(&g_colsum[threadIdx.x], scol[threadIdx.x]);

    if (threadIdx.x == 0) {
        float bs = 0.f;
        #pragma unroll
        for (int wv = 0; wv < MAIN_BLOCK / 32; wv++) bs += swarp[wv];
        atomicAdd(&g_scalar, bs);
    }
}

__global__ void finalize_kernel(float* __restrict__ out)
{
    __shared__ float sh[128];
    int t = threadIdx.x;
    float v = (t < NUM_CITIES) ? logf(g_colsum[t]) : 0.0f;
    sh[t] = v;
    __syncthreads();
    for (int off = 64; off > 0; off >>= 1) {
        if (t < off) sh[t] += sh[t + off];
        __syncthreads();
    }
    if (t == 0) {
        // loss = scalar_terms + stddeve^2 * lgg   (stddeve^2 = 1e-4)
        out[0] = g_scalar + 1.0e-4f * sh[0];
    }
}

extern "C" void kernel_launch(void* const* d_in, const int* in_sizes, int n_in,
                              void* d_out, int out_size)
{
    // metadata order: G, out, U, V, D, w   (V unused)
    const float4* G4  = (const float4*)d_in[0];
    const float*  OUT = (const float*) d_in[1];
    const float*  U   = (const float*) d_in[2];
    const float4* D4  = (const float4*)d_in[4];
    const float4* W4  = (const float4*)d_in[5];
    float* out = (float*)d_out;

    zero_kernel<<<1, 96>>>();
    main_kernel<<<MAIN_GRID, MAIN_BLOCK>>>(G4, D4, W4, U, OUT);
    finalize_kernel<<<1, 128>>>(out);
}

// round 6
// speedup vs baseline: 1.0942x; 1.0925x over previous
#include <cuda_runtime.h>
#include <math.h>

#define NUM_CITIES 88
#define NC4        22          // 88 / 4 float4 groups per row
#define NUM_YEARS  6
#define N_ROWS     200000

#define MAIN_BLOCK 352         // 22 * 16 -> every block is column-group aligned
#define MAIN_GRID  592         // 148 SMs * 4 resident blocks, one wave

// Scratch accumulators. Zero-initialized at module load; the last block of
// every launch resets them to zero again, so each launch (and each graph
// replay) starts from a clean state. No separate zero/finalize kernels.
__device__ float g_colsum[NUM_CITIES];
__device__ float g_scalar;
__device__ unsigned int g_count;

__global__ __launch_bounds__(MAIN_BLOCK, 4)
void fused_loss_kernel(const float4* __restrict__ G4,
                       const float4* __restrict__ D4,
                       const float4* __restrict__ W4,
                       const float*  __restrict__ U,
                       const float*  __restrict__ OUT,
                       float* __restrict__ out)
{
    const int tid    = blockIdx.x * MAIN_BLOCK + threadIdx.x;
    const int total  = gridDim.x * MAIN_BLOCK;          // multiple of 22
    const int lanes  = total / NC4;                     // row-stride lanes
    const int cg     = tid % NC4;                       // fixed column group
    const int lane   = tid / NC4;

    // --- per-thread accumulators ---
    float c0 = 0.f, c1 = 0.f, c2 = 0.f, c3 = 0.f;       // |G| column partials
    float s  = 0.f;                                     // scalar loss partial

    // Term 1: ||U[:, :5] - out[:, :5]||_F^2  (9.6 MB; each thread does <=1 row)
    for (int r = tid; r < N_ROWS; r += total) {
        const float* u = U   + r * NUM_YEARS;
        const float* o = OUT + r * NUM_YEARS;
        #pragma unroll
        for (int j = 0; j < NUM_YEARS - 1; j++) {
            float d = u[j] - o[j];
            s += d * d;
        }
    }

    // Main stream: G, D, w (211 MB). Thread stays in one 4-col group so the
    // |G| column partials live in 4 registers. Warp-contiguous addresses.
    for (int r = lane; r < N_ROWS; r += lanes) {
        int i = r * NC4 + cg;
        float4 g = __ldcs(&G4[i]);      // read-once: evict-first
        float4 d = __ldcs(&D4[i]);
        float4 w = __ldcs(&W4[i]);

        // column L1 of |G|
        c0 += fabsf(g.x); c1 += fabsf(g.y);
        c2 += fabsf(g.z); c3 += fabsf(g.w);

        // 100 * ||G - w*D||^2
        float r0 = fmaf(-w.x, d.x, g.x);
        float r1 = fmaf(-w.y, d.y, g.y);
        float r2 = fmaf(-w.z, d.z, g.z);
        float r3 = fmaf(-w.w, d.w, g.w);
        s += 100.0f * (r0*r0 + r1*r1 + r2*r2 + r3*r3);

        // 0.01 * ||w||^2
        s += 0.01f * (w.x*w.x + w.y*w.y + w.z*w.z + w.w*w.w);

        // 100 * sum(min(G, 0))
        s += 100.0f * (fminf(g.x, 0.f) + fminf(g.y, 0.f)
                     + fminf(g.z, 0.f) + fminf(g.w, 0.f));
    }

    // --- block-level reduction ---
    __shared__ float scol[NUM_CITIES];
    __shared__ float swarp[MAIN_BLOCK / 32];
    __shared__ unsigned int is_last;

    if (threadIdx.x < NUM_CITIES) scol[threadIdx.x] = 0.0f;
    __syncthreads();

    // column partials: 16 threads per shared slot, once per block
    atomicAdd(&scol[cg * 4 + 0], c0);
    atomicAdd(&scol[cg * 4 + 1], c1);
    atomicAdd(&scol[cg * 4 + 2], c2);
    atomicAdd(&scol[cg * 4 + 3], c3);

    // scalar: warp shuffle reduce
    #pragma unroll
    for (int off = 16; off > 0; off >>= 1)
        s += __shfl_xor_sync(0xFFFFFFFF, s, off);
    if ((threadIdx.x & 31) == 0) swarp[threadIdx.x >> 5] = s;
    __syncthreads();

    // --- grid-level accumulation into device globals ---
    if (threadIdx.x < NUM_CITIES)
        atomicAdd(&g_colsum[threadIdx.x], scol[threadIdx.x]);

    if (threadIdx.x == 0) {
        float bs = 0.f;
        #pragma unroll
        for (int wv = 0; wv < MAIN_BLOCK / 32; wv++) bs += swarp[wv];
        atomicAdd(&g_scalar, bs);
    }

    // --- last-block finalize (threadFenceReduction pattern) ---
    __threadfence();
    __syncthreads();
    if (threadIdx.x == 0)
        is_last = (atomicAdd(&g_count, 1u) == (unsigned)(gridDim.x - 1));
    __syncthreads();
    if (!is_last) return;

    __threadfence();   // acquire: all blocks' atomics now visible

    __shared__ float sh[128];
    int t = threadIdx.x;
    if (t < 128) {
        float v = 0.0f;
        if (t < NUM_CITIES) {
            v = logf(*((volatile float*)&g_colsum[t]));
            *((volatile float*)&g_colsum[t]) = 0.0f;   // reset for next launch
        }
        sh[t] = v;
    }
    __syncthreads();
    #pragma unroll
    for (int off = 64; off > 0; off >>= 1) {
        if (t < off) sh[t] += sh[t + off];
        __syncthreads();
    }
    if (t == 0) {
        float sc = *((volatile float*)&g_scalar);
        // loss = scalar_terms + stddeve^2 * lgg   (stddeve^2 = 1e-4)
        out[0] = sc + 1.0e-4f * sh[0];
        *((volatile float*)&g_scalar) = 0.0f;          // reset for next launch
        g_count = 0u;                                  // reset ticket counter
    }
}

extern "C" void kernel_launch(void* const* d_in, const int* in_sizes, int n_in,
                              void* d_out, int out_size)
{
    // metadata order: G, out, U, V, D, w   (V unused by the loss)
    const float4* G4  = (const float4*)d_in[0];
    const float*  OUT = (const float*) d_in[1];
    const float*  U   = (const float*) d_in[2];
    const float4* D4  = (const float4*)d_in[4];
    const float4* W4  = (const float4*)d_in[5];
    float* out = (float*)d_out;

    fused_loss_kernel<<<MAIN_GRID, MAIN_BLOCK>>>(G4, D4, W4, U, OUT, out);
}